// round 13
// baseline (speedup 1.0000x reference)
#include <cuda_runtime.h>
#include <cuda_fp16.h>
#include <cstdint>
#include <math.h>

// ---------------------------------------------------------------- constants
constexpr int Bz   = 4;
constexpr int Lseq = 4096;
constexpr int Dm   = 2048;
constexpr int Mtot = Bz * Lseq;                 // 16384
constexpr float SCALE = 0.08838834764831845f;   // 128^-0.5

constexpr int NC = 128;                         // scan chunks
constexpr int CH = Lseq / NC;                   // 32

// GEMM tiling: CTA 128x256, 8 warps of 64x64, BK=64, 4-stage cp.async
constexpr int BM = 128, BN = 256, BK = 64;
constexpr int STAGES = 4;
constexpr int KT = Dm / BK;                       // 32
constexpr int ROWB = 144;                         // 128B data + 16B pad
constexpr int A_TILE = BM * ROWB;                 // 18432 bytes
constexpr int B_TILE = BN * ROWB;                 // 36864 bytes
constexpr int STAGE_BYTES = A_TILE + B_TILE;      // 55296
constexpr int SMEM_TOTAL  = STAGES * STAGE_BYTES; // 221184

constexpr int NX4 = Mtot * Dm / 4;                // 8388608  (2^23)
constexpr int NW4 = Dm * Dm / 4;                  // 1048576  (2^20)

constexpr int SCAN_SMEM = CH * 256 * 16;          // 131072 bytes
constexpr int NFLAGS = Bz * NC * 2;               // 1024

// ---------------------------------------------------------------- scratch
__device__ __half g_xh  [(size_t)Mtot * Dm];
__device__ __half g_wh  [4][(size_t)Dm * Dm];
__device__ __half g_phiq[(size_t)Mtot * Dm];
__device__ __half g_phik[(size_t)Mtot * Dm];
__device__ __half g_v   [(size_t)Mtot * Dm];
__device__ __half g_ctxh[(size_t)Mtot * Dm];
__device__ float  g_part[(size_t)Bz * NC * Dm];
__device__ int    g_flags[NFLAGS];

// ---------------------------------------------------------------- helpers
__device__ __forceinline__ uint32_t smem_u32(const void* p) {
    uint32_t a;
    asm("{ .reg .u64 t; cvta.to.shared.u64 t, %1; cvt.u32.u64 %0, t; }"
        : "=r"(a) : "l"(p));
    return a;
}
__device__ __forceinline__ void cp16(uint32_t dst, const void* src) {
    asm volatile("cp.async.cg.shared.global [%0], [%1], 16;"
                 :: "r"(dst), "l"(src) : "memory");
}
__device__ __forceinline__ void mma_f16(float* d, const uint32_t* a,
                                        const uint32_t* b) {
    asm volatile(
        "mma.sync.aligned.m16n8k16.row.col.f32.f16.f16.f32 "
        "{%0,%1,%2,%3}, {%4,%5,%6,%7}, {%8,%9}, {%0,%1,%2,%3};"
        : "+f"(d[0]), "+f"(d[1]), "+f"(d[2]), "+f"(d[3])
        : "r"(a[0]), "r"(a[1]), "r"(a[2]), "r"(a[3]), "r"(b[0]), "r"(b[1]));
}
__device__ __forceinline__ void ldsm4(uint32_t* r, uint32_t addr) {
    asm volatile("ldmatrix.sync.aligned.m8n8.x4.shared.b16 {%0,%1,%2,%3}, [%4];"
                 : "=r"(r[0]), "=r"(r[1]), "=r"(r[2]), "=r"(r[3]) : "r"(addr));
}
__device__ __forceinline__ uint32_t pack_h2(float a, float b) {
    __half2 h = __floats2half2_rn(a, b);
    return *(const uint32_t*)&h;
}
__device__ __forceinline__ float2 unpack_h2(uint32_t u) {
    return __half22float2(*(const __half2*)&u);
}

// ------------------------------------------------------------------- GEMM
// C[M][N] = act(A[M][K] @ W[N][K]^T + bias[N]); fp16 in, fp32 accumulate.
template<typename OutT>
__device__ __forceinline__ void gemm_body(
    const __half* __restrict__ A, const __half* __restrict__ W,
    const float* __restrict__ bias, OutT* __restrict__ C, int act)
{
    extern __shared__ float smem[];
    const uint32_t sb = smem_u32(smem);
    const int tid  = threadIdx.x;
    const int wid  = tid >> 5;
    const int lane = tid & 31;
    const int wm = wid & 1;
    const int wn = wid >> 1;
    const int gq = lane >> 2;
    const int gr = lane & 3;
    const int m0 = blockIdx.y * BM;
    const int n0 = blockIdx.x * BN;

    uint32_t offA[4], offB[4];
#pragma unroll
    for (int mt = 0; mt < 4; mt++) {
        int row = wm * 64 + mt * 16 + ((lane >> 3) & 1) * 8 + (lane & 7);
        offA[mt] = (uint32_t)(row * ROWB + ((lane >> 4) * 16));
    }
#pragma unroll
    for (int p = 0; p < 4; p++) {
        int row = wn * 64 + p * 16 + (lane >> 4) * 8 + (lane & 7);
        offB[p] = (uint32_t)(row * ROWB + (((lane >> 3) & 1) * 16));
    }

    float acc[4][8][4];
#pragma unroll
    for (int i = 0; i < 4; i++)
#pragma unroll
        for (int j = 0; j < 8; j++)
#pragma unroll
            for (int k = 0; k < 4; k++) acc[i][j][k] = 0.f;

    auto issue = [&](int kt) {
        const int s = kt & (STAGES - 1);
        const uint32_t dA = sb + s * STAGE_BYTES;
        const uint32_t dB = dA + A_TILE;
        const __half* Ag = A + (size_t)m0 * Dm + kt * BK;
        const __half* Wg = W + (size_t)n0 * Dm + kt * BK;
#pragma unroll
        for (int i = 0; i < 4; i++) {
            int ch = tid + 256 * i, row = ch >> 3, c4 = ch & 7;
            cp16(dA + row * ROWB + c4 * 16, Ag + (size_t)row * Dm + c4 * 8);
        }
#pragma unroll
        for (int i = 0; i < 8; i++) {
            int ch = tid + 256 * i, row = ch >> 3, c4 = ch & 7;
            cp16(dB + row * ROWB + c4 * 16, Wg + (size_t)row * Dm + c4 * 8);
        }
        asm volatile("cp.async.commit_group;" ::: "memory");
    };

    issue(0);
    issue(1);
    issue(2);

    for (int kt = 0; kt < KT; kt++) {
        const int s = kt & (STAGES - 1);
        asm volatile("cp.async.wait_group 2;" ::: "memory");
        __syncthreads();

        if (kt + 3 < KT) issue(kt + 3);
        else asm volatile("cp.async.commit_group;" ::: "memory");

        const uint32_t aBase = sb + s * STAGE_BYTES;
        const uint32_t bBase = aBase + A_TILE;

#pragma unroll
        for (int ks = 0; ks < 4; ks++) {
            const uint32_t kOfs = ks * 32;
            uint32_t af[4][4], bfr[16];
#pragma unroll
            for (int mt = 0; mt < 4; mt++)
                ldsm4(af[mt], aBase + offA[mt] + kOfs);
#pragma unroll
            for (int p = 0; p < 4; p++)
                ldsm4(&bfr[4 * p], bBase + offB[p] + kOfs);
#pragma unroll
            for (int mt = 0; mt < 4; mt++)
#pragma unroll
                for (int nt = 0; nt < 8; nt++)
                    mma_f16(acc[mt][nt], af[mt], &bfr[2 * nt]);
        }
    }

    // ----------------------------- epilogue --------------------------------
#pragma unroll
    for (int mt = 0; mt < 4; mt++) {
        const int r0 = m0 + wm * 64 + mt * 16 + gq;
#pragma unroll
        for (int nt = 0; nt < 8; nt++) {
            const int c0 = n0 + wn * 64 + nt * 8 + gr * 2;
            float b0 = bias[c0], b1 = bias[c0 + 1];
            float v0 = acc[mt][nt][0] + b0;
            float v1 = acc[mt][nt][1] + b1;
            float v2 = acc[mt][nt][2] + b0;
            float v3 = acc[mt][nt][3] + b1;
            if (act) {
                v0 = (v0 > 0.f) ? (v0 + 1.f) : expf(v0);
                v1 = (v1 > 0.f) ? (v1 + 1.f) : expf(v1);
                v2 = (v2 > 0.f) ? (v2 + 1.f) : expf(v2);
                v3 = (v3 > 0.f) ? (v3 + 1.f) : expf(v3);
            }
            if constexpr (sizeof(OutT) == 2) {
                *(uint32_t*)(C + (size_t)r0 * Dm + c0)       = pack_h2(v0, v1);
                *(uint32_t*)(C + (size_t)(r0 + 8) * Dm + c0) = pack_h2(v2, v3);
            } else {
                *(float2*)(C + (size_t)r0 * Dm + c0)       = make_float2(v0, v1);
                *(float2*)(C + (size_t)(r0 + 8) * Dm + c0) = make_float2(v2, v3);
            }
        }
    }
}

// fused QKV: blockIdx.z selects projection; outputs fp16
__global__ void __launch_bounds__(256, 1)
gemm_qkv(const __half* __restrict__ x,
         const __half* __restrict__ Wq, const float* __restrict__ bq,
         const __half* __restrict__ Wk, const float* __restrict__ bk,
         const __half* __restrict__ Wv, const float* __restrict__ bv,
         __half* __restrict__ phiq, __half* __restrict__ phik,
         __half* __restrict__ v)
{
    const int z = blockIdx.z;
    const __half* W   = (z == 0) ? Wq : (z == 1) ? Wk : Wv;
    const float* bias = (z == 0) ? bq : (z == 1) ? bk : bv;
    __half* C         = (z == 0) ? phiq : (z == 1) ? phik : v;
    gemm_body<__half>(x, W, bias, C, z < 2 ? 1 : 0);
}

__global__ void __launch_bounds__(256, 1)
gemm_o(const __half* __restrict__ A, const __half* __restrict__ W,
       const float* __restrict__ bias, float* __restrict__ C)
{
    gemm_body<float>(A, W, bias, C, 0);
}

// ------------------------------------------------------------ fused convert
// One launch converts x + the four weight matrices to fp16, and resets the
// scan lookback flags (must be re-zeroed on every graph replay).
__global__ void __launch_bounds__(256)
to_half_all(const float4* __restrict__ x,
            const float4* __restrict__ Wq, const float4* __restrict__ Wk,
            const float4* __restrict__ Wv, const float4* __restrict__ Wo,
            uint2* __restrict__ xh, uint2* __restrict__ wh,
            int* __restrict__ flags)
{
    int i = blockIdx.x * 256 + threadIdx.x;
    if (i < NFLAGS) flags[i] = 0;
    const float4* src;
    uint2* dst;
    int j;
    if (i < NX4) {
        src = x; dst = xh; j = i;
    } else {
        int t = i - NX4;
        int r = t >> 20;           // NW4 = 2^20
        j = t & (NW4 - 1);
        src = (r == 0) ? Wq : (r == 1) ? Wk : (r == 2) ? Wv : Wo;
        dst = wh + (size_t)r * NW4;
    }
    float4 v = src[j];
    uint2 u;
    u.x = pack_h2(v.x, v.y);
    u.y = pack_h2(v.z, v.w);
    dst[j] = u;
}

// --------------------------------------------------- single-pass fused scan
// Block (x, c, b): 256 threads, each owns one float4-channel group.
// Pass 1: chunk sum (products cached in smem). Publish. Lookback. Pass 2: ctx.
__global__ void __launch_bounds__(256, 1)
scan_fused(const uint2* __restrict__ pq, const uint2* __restrict__ pk,
           const uint2* __restrict__ pv, float4* __restrict__ part,
           int* __restrict__ flags, uint2* __restrict__ ctxh)
{
    extern __shared__ float4 prod[];      // [CH][256]
    constexpr int D4 = Dm / 4;            // 512
    const int tid = threadIdx.x;
    const int x = blockIdx.x;             // 0..1 (d-block)
    const int c = blockIdx.y;             // 0..NC-1 (chunk)
    const int b = blockIdx.z;
    const int d = x * 256 + tid;
    const size_t base = ((size_t)b * Lseq + (size_t)c * CH) * D4 + d;

    // pass 1: products + chunk sum
    float4 s = make_float4(0.f, 0.f, 0.f, 0.f);
#pragma unroll 4
    for (int i = 0; i < CH; i++) {
        size_t idx = base + (size_t)i * D4;
        uint2 ku = pk[idx], vu = pv[idx];
        float2 k01 = unpack_h2(ku.x), k23 = unpack_h2(ku.y);
        float2 v01 = unpack_h2(vu.x), v23 = unpack_h2(vu.y);
        float4 p;
        p.x = k01.x * v01.x; p.y = k01.y * v01.y;
        p.z = k23.x * v23.x; p.w = k23.y * v23.y;
        prod[i * 256 + tid] = p;
        s.x += p.x; s.y += p.y; s.z += p.z; s.w += p.w;
    }
    part[((size_t)b * NC + c) * D4 + d] = s;
    __threadfence();
    atomicAdd(&flags[(b * NC + c) * 2 + x], 1);   // release: this thread done

    // lookback wait: thread t waits for chunk t (t < c)
    if (tid < c) {
        int* f = &flags[(b * NC + tid) * 2 + x];
        while (atomicAdd(f, 0) < 256) { __nanosleep(64); }
    }
    __syncthreads();
    __threadfence();                               // acquire

    // exclusive prefix over published chunk sums (L2 reads, bypass L1)
    float4 run = make_float4(0.f, 0.f, 0.f, 0.f);
    for (int cc = 0; cc < c; cc++) {
        const float4* pp = &part[((size_t)b * NC + cc) * D4 + d];
        float4 t = __ldcg(pp);
        run.x += t.x; run.y += t.y; run.z += t.z; run.w += t.w;
    }

    // pass 2: running prefix within chunk, gate by phi_q * SCALE
#pragma unroll 4
    for (int i = 0; i < CH; i++) {
        size_t idx = base + (size_t)i * D4;
        float4 p = prod[i * 256 + tid];
        run.x += p.x; run.y += p.y; run.z += p.z; run.w += p.w;
        uint2 qu = pq[idx];
        float2 q01 = unpack_h2(qu.x), q23 = unpack_h2(qu.y);
        uint2 u;
        u.x = pack_h2(q01.x * run.x * SCALE, q01.y * run.y * SCALE);
        u.y = pack_h2(q23.x * run.z * SCALE, q23.y * run.w * SCALE);
        ctxh[idx] = u;
    }
}

// ---------------------------------------------------------------- launch
extern "C" void kernel_launch(void* const* d_in, const int* in_sizes, int n_in,
                              void* d_out, int out_size)
{
    const float* x  = (const float*)d_in[0];
    const float* Wq = (const float*)d_in[1];
    const float* bq = (const float*)d_in[2];
    const float* Wk = (const float*)d_in[3];
    const float* bk = (const float*)d_in[4];
    const float* Wv = (const float*)d_in[5];
    const float* bv = (const float*)d_in[6];
    const float* Wo = (const float*)d_in[7];
    const float* bo = (const float*)d_in[8];
    float* out = (float*)d_out;

    __half *xh, *wh, *ctxh, *phiq, *phik, *v;
    float *part;
    int *flags;
    cudaGetSymbolAddress((void**)&xh,    g_xh);
    cudaGetSymbolAddress((void**)&wh,    g_wh);
    cudaGetSymbolAddress((void**)&ctxh,  g_ctxh);
    cudaGetSymbolAddress((void**)&phiq,  g_phiq);
    cudaGetSymbolAddress((void**)&phik,  g_phik);
    cudaGetSymbolAddress((void**)&v,     g_v);
    cudaGetSymbolAddress((void**)&part,  g_part);
    cudaGetSymbolAddress((void**)&flags, g_flags);
    __half* whq = wh;
    __half* whk = wh + (size_t)Dm * Dm;
    __half* whv = wh + 2 * (size_t)Dm * Dm;
    __half* who = wh + 3 * (size_t)Dm * Dm;

    static bool attr_set = false;
    if (!attr_set) {
        cudaFuncSetAttribute(gemm_qkv,  cudaFuncAttributeMaxDynamicSharedMemorySize, SMEM_TOTAL);
        cudaFuncSetAttribute(gemm_o,    cudaFuncAttributeMaxDynamicSharedMemorySize, SMEM_TOTAL);
        cudaFuncSetAttribute(scan_fused, cudaFuncAttributeMaxDynamicSharedMemorySize, SCAN_SMEM);
        attr_set = true;
    }

    // one fused fp16 conversion pass (also clears scan flags for this replay)
    const int nTot = NX4 + 4 * NW4;
    to_half_all<<<(nTot + 255) / 256, 256>>>(
        (const float4*)x, (const float4*)Wq, (const float4*)Wk,
        (const float4*)Wv, (const float4*)Wo, (uint2*)xh, (uint2*)wh, flags);

    dim3 qkvgrid(Dm / BN, Mtot / BM, 3);   // (8, 128, 3)
    gemm_qkv<<<qkvgrid, 256, SMEM_TOTAL>>>(xh, whq, bq, whk, bk, whv, bv,
                                           phiq, phik, v);

    dim3 sgrid(Dm / 4 / 256, NC, Bz);      // (2, 128, 4) = 1024 blocks
    scan_fused<<<sgrid, 256, SCAN_SMEM>>>((const uint2*)phiq,
                                          (const uint2*)phik,
                                          (const uint2*)v,
                                          (float4*)part, flags,
                                          (uint2*)ctxh);

    dim3 ogrid(Dm / BN, Mtot / BM);        // (8, 128)
    gemm_o<<<ogrid, 256, SMEM_TOTAL>>>(ctxh, who, bo, out);
}

// round 14
// speedup vs baseline: 1.0272x; 1.0272x over previous
#include <cuda_runtime.h>
#include <cuda_fp16.h>
#include <cstdint>
#include <math.h>

// ---------------------------------------------------------------- constants
constexpr int Bz   = 4;
constexpr int Lseq = 4096;
constexpr int Dm   = 2048;
constexpr int Mtot = Bz * Lseq;                 // 16384
constexpr float SCALE = 0.08838834764831845f;   // 128^-0.5

constexpr int NC = 64;                          // scan chunks
constexpr int CH = Lseq / NC;                   // 64

// GEMM tiling: CTA 128x256, 8 warps of 64x64, BK=64, 4-stage cp.async
constexpr int BM = 128, BN = 256, BK = 64;
constexpr int STAGES = 4;
constexpr int KT = Dm / BK;                       // 32
constexpr int ROWB = 144;                         // 128B data + 16B pad
constexpr int A_TILE = BM * ROWB;                 // 18432 bytes
constexpr int B_TILE = BN * ROWB;                 // 36864 bytes
constexpr int STAGE_BYTES = A_TILE + B_TILE;      // 55296
constexpr int SMEM_TOTAL  = STAGES * STAGE_BYTES; // 221184

constexpr int NX4 = Mtot * Dm / 4;                // 8388608  (2^23)
constexpr int NW4 = Dm * Dm / 4;                  // 1048576  (2^20)

// ---------------------------------------------------------------- scratch
__device__ __half g_xh  [(size_t)Mtot * Dm];
__device__ __half g_wh  [4][(size_t)Dm * Dm];
__device__ __half g_phiq[(size_t)Mtot * Dm];
__device__ __half g_phik[(size_t)Mtot * Dm];
__device__ __half g_v   [(size_t)Mtot * Dm];
__device__ __half g_ctxh[(size_t)Mtot * Dm];
__device__ float  g_part[(size_t)Bz * NC * Dm];

// ---------------------------------------------------------------- helpers
__device__ __forceinline__ uint32_t smem_u32(const void* p) {
    uint32_t a;
    asm("{ .reg .u64 t; cvta.to.shared.u64 t, %1; cvt.u32.u64 %0, t; }"
        : "=r"(a) : "l"(p));
    return a;
}
__device__ __forceinline__ void cp16(uint32_t dst, const void* src) {
    asm volatile("cp.async.cg.shared.global [%0], [%1], 16;"
                 :: "r"(dst), "l"(src) : "memory");
}
__device__ __forceinline__ void mma_f16(float* d, const uint32_t* a,
                                        const uint32_t* b) {
    asm volatile(
        "mma.sync.aligned.m16n8k16.row.col.f32.f16.f16.f32 "
        "{%0,%1,%2,%3}, {%4,%5,%6,%7}, {%8,%9}, {%0,%1,%2,%3};"
        : "+f"(d[0]), "+f"(d[1]), "+f"(d[2]), "+f"(d[3])
        : "r"(a[0]), "r"(a[1]), "r"(a[2]), "r"(a[3]), "r"(b[0]), "r"(b[1]));
}
__device__ __forceinline__ void ldsm4(uint32_t* r, uint32_t addr) {
    asm volatile("ldmatrix.sync.aligned.m8n8.x4.shared.b16 {%0,%1,%2,%3}, [%4];"
                 : "=r"(r[0]), "=r"(r[1]), "=r"(r[2]), "=r"(r[3]) : "r"(addr));
}
__device__ __forceinline__ uint32_t pack_h2(float a, float b) {
    __half2 h = __floats2half2_rn(a, b);
    return *(const uint32_t*)&h;
}
__device__ __forceinline__ float2 unpack_h2(uint32_t u) {
    return __half22float2(*(const __half2*)&u);
}

// ------------------------------------------------------------------- GEMM
// C[M][N] = act(A[M][K] @ W[N][K]^T + bias[N]); fp16 in, fp32 accumulate.
// Fragment loads double-buffered: ldsm for ks+1 issues before mma for ks.
template<typename OutT>
__device__ __forceinline__ void gemm_body(
    const __half* __restrict__ A, const __half* __restrict__ W,
    const float* __restrict__ bias, OutT* __restrict__ C, int act)
{
    extern __shared__ float smem[];
    const uint32_t sb = smem_u32(smem);
    const int tid  = threadIdx.x;
    const int wid  = tid >> 5;
    const int lane = tid & 31;
    const int wm = wid & 1;
    const int wn = wid >> 1;
    const int gq = lane >> 2;
    const int gr = lane & 3;
    const int m0 = blockIdx.y * BM;
    const int n0 = blockIdx.x * BN;

    uint32_t offA[4], offB[4];
#pragma unroll
    for (int mt = 0; mt < 4; mt++) {
        int row = wm * 64 + mt * 16 + ((lane >> 3) & 1) * 8 + (lane & 7);
        offA[mt] = (uint32_t)(row * ROWB + ((lane >> 4) * 16));
    }
#pragma unroll
    for (int p = 0; p < 4; p++) {
        int row = wn * 64 + p * 16 + (lane >> 4) * 8 + (lane & 7);
        offB[p] = (uint32_t)(row * ROWB + (((lane >> 3) & 1) * 16));
    }

    float acc[4][8][4];
#pragma unroll
    for (int i = 0; i < 4; i++)
#pragma unroll
        for (int j = 0; j < 8; j++)
#pragma unroll
            for (int k = 0; k < 4; k++) acc[i][j][k] = 0.f;

    auto issue = [&](int kt) {
        const int s = kt & (STAGES - 1);
        const uint32_t dA = sb + s * STAGE_BYTES;
        const uint32_t dB = dA + A_TILE;
        const __half* Ag = A + (size_t)m0 * Dm + kt * BK;
        const __half* Wg = W + (size_t)n0 * Dm + kt * BK;
#pragma unroll
        for (int i = 0; i < 4; i++) {
            int ch = tid + 256 * i, row = ch >> 3, c4 = ch & 7;
            cp16(dA + row * ROWB + c4 * 16, Ag + (size_t)row * Dm + c4 * 8);
        }
#pragma unroll
        for (int i = 0; i < 8; i++) {
            int ch = tid + 256 * i, row = ch >> 3, c4 = ch & 7;
            cp16(dB + row * ROWB + c4 * 16, Wg + (size_t)row * Dm + c4 * 8);
        }
        asm volatile("cp.async.commit_group;" ::: "memory");
    };

    issue(0);
    issue(1);
    issue(2);

    uint32_t af[2][4][4], bfr[2][16];   // double-buffered fragments

    auto load_frags = [&](uint32_t aBase, uint32_t bBase, int ks, int buf) {
        const uint32_t kOfs = ks * 32;
#pragma unroll
        for (int mt = 0; mt < 4; mt++)
            ldsm4(af[buf][mt], aBase + offA[mt] + kOfs);
#pragma unroll
        for (int p = 0; p < 4; p++)
            ldsm4(&bfr[buf][4 * p], bBase + offB[p] + kOfs);
    };
    auto do_mma = [&](int buf) {
#pragma unroll
        for (int mt = 0; mt < 4; mt++)
#pragma unroll
            for (int nt = 0; nt < 8; nt++)
                mma_f16(acc[mt][nt], af[buf][mt], &bfr[buf][2 * nt]);
    };

    for (int kt = 0; kt < KT; kt++) {
        const int s = kt & (STAGES - 1);
        asm volatile("cp.async.wait_group 2;" ::: "memory");
        __syncthreads();

        if (kt + 3 < KT) issue(kt + 3);
        else asm volatile("cp.async.commit_group;" ::: "memory");

        const uint32_t aBase = sb + s * STAGE_BYTES;
        const uint32_t bBase = aBase + A_TILE;

        load_frags(aBase, bBase, 0, 0);
#pragma unroll
        for (int ks = 0; ks < 4; ks++) {
            if (ks < 3) load_frags(aBase, bBase, ks + 1, (ks + 1) & 1);
            do_mma(ks & 1);
        }
    }

    // ----------------------------- epilogue --------------------------------
#pragma unroll
    for (int mt = 0; mt < 4; mt++) {
        const int r0 = m0 + wm * 64 + mt * 16 + gq;
#pragma unroll
        for (int nt = 0; nt < 8; nt++) {
            const int c0 = n0 + wn * 64 + nt * 8 + gr * 2;
            float b0 = bias[c0], b1 = bias[c0 + 1];
            float v0 = acc[mt][nt][0] + b0;
            float v1 = acc[mt][nt][1] + b1;
            float v2 = acc[mt][nt][2] + b0;
            float v3 = acc[mt][nt][3] + b1;
            if (act) {
                v0 = (v0 > 0.f) ? (v0 + 1.f) : expf(v0);
                v1 = (v1 > 0.f) ? (v1 + 1.f) : expf(v1);
                v2 = (v2 > 0.f) ? (v2 + 1.f) : expf(v2);
                v3 = (v3 > 0.f) ? (v3 + 1.f) : expf(v3);
            }
            if constexpr (sizeof(OutT) == 2) {
                *(uint32_t*)(C + (size_t)r0 * Dm + c0)       = pack_h2(v0, v1);
                *(uint32_t*)(C + (size_t)(r0 + 8) * Dm + c0) = pack_h2(v2, v3);
            } else {
                *(float2*)(C + (size_t)r0 * Dm + c0)       = make_float2(v0, v1);
                *(float2*)(C + (size_t)(r0 + 8) * Dm + c0) = make_float2(v2, v3);
            }
        }
    }
}

// fused QKV: blockIdx.z selects projection; outputs fp16
__global__ void __launch_bounds__(256, 1)
gemm_qkv(const __half* __restrict__ x,
         const __half* __restrict__ Wq, const float* __restrict__ bq,
         const __half* __restrict__ Wk, const float* __restrict__ bk,
         const __half* __restrict__ Wv, const float* __restrict__ bv,
         __half* __restrict__ phiq, __half* __restrict__ phik,
         __half* __restrict__ v)
{
    const int z = blockIdx.z;
    const __half* W   = (z == 0) ? Wq : (z == 1) ? Wk : Wv;
    const float* bias = (z == 0) ? bq : (z == 1) ? bk : bv;
    __half* C         = (z == 0) ? phiq : (z == 1) ? phik : v;
    gemm_body<__half>(x, W, bias, C, z < 2 ? 1 : 0);
}

__global__ void __launch_bounds__(256, 1)
gemm_o(const __half* __restrict__ A, const __half* __restrict__ W,
       const float* __restrict__ bias, float* __restrict__ C)
{
    gemm_body<float>(A, W, bias, C, 0);
}

// ------------------------------------------------------------ fused convert
__global__ void __launch_bounds__(256)
to_half_all(const float4* __restrict__ x,
            const float4* __restrict__ Wq, const float4* __restrict__ Wk,
            const float4* __restrict__ Wv, const float4* __restrict__ Wo,
            uint2* __restrict__ xh, uint2* __restrict__ wh)
{
    int i = blockIdx.x * 256 + threadIdx.x;
    const float4* src;
    uint2* dst;
    int j;
    if (i < NX4) {
        src = x; dst = xh; j = i;
    } else {
        int t = i - NX4;
        int r = t >> 20;           // NW4 = 2^20
        j = t & (NW4 - 1);
        src = (r == 0) ? Wq : (r == 1) ? Wk : (r == 2) ? Wv : Wo;
        dst = wh + (size_t)r * NW4;
    }
    float4 v = src[j];
    uint2 u;
    u.x = pack_h2(v.x, v.y);
    u.y = pack_h2(v.z, v.w);
    dst[j] = u;
}

// ---------------------------------------------------------------- scan stage
__global__ void chunk_partial(const uint2* __restrict__ pk,
                              const uint2* __restrict__ pv,
                              float4* __restrict__ part)
{
    constexpr int D4 = Dm / 4;
    const int d = blockIdx.x * 256 + threadIdx.x;
    const int c = blockIdx.y;
    const int b = blockIdx.z;
    size_t base = ((size_t)b * Lseq + (size_t)c * CH) * D4 + d;
    float4 s = make_float4(0.f, 0.f, 0.f, 0.f);
#pragma unroll 4
    for (int i = 0; i < CH; i++) {
        size_t idx = base + (size_t)i * D4;
        uint2 ku = pk[idx], vu = pv[idx];
        float2 k01 = unpack_h2(ku.x), k23 = unpack_h2(ku.y);
        float2 v01 = unpack_h2(vu.x), v23 = unpack_h2(vu.y);
        s.x += k01.x * v01.x; s.y += k01.y * v01.y;
        s.z += k23.x * v23.x; s.w += k23.y * v23.y;
    }
    part[((size_t)b * NC + c) * D4 + d] = s;
}

__global__ void scan_partials(float4* __restrict__ part)
{
    constexpr int D4 = Dm / 4;
    const int d = blockIdx.x * 256 + threadIdx.x;
    const int b = blockIdx.y;
    float4 run = make_float4(0.f, 0.f, 0.f, 0.f);
    for (int c = 0; c < NC; c++) {
        size_t idx = ((size_t)b * NC + c) * D4 + d;
        float4 t = part[idx];
        part[idx] = run;
        run.x += t.x; run.y += t.y; run.z += t.z; run.w += t.w;
    }
}

__global__ void apply_scan(const uint2* __restrict__ pq,
                           const uint2* __restrict__ pk,
                           const uint2* __restrict__ pv,
                           const float4* __restrict__ part,
                           uint2* __restrict__ ctxh)
{
    constexpr int D4 = Dm / 4;
    const int d = blockIdx.x * 256 + threadIdx.x;
    const int c = blockIdx.y;
    const int b = blockIdx.z;
    float4 run = part[((size_t)b * NC + c) * D4 + d];
    size_t base = ((size_t)b * Lseq + (size_t)c * CH) * D4 + d;
#pragma unroll 4
    for (int i = 0; i < CH; i++) {
        size_t idx = base + (size_t)i * D4;
        uint2 ku = pk[idx], vu = pv[idx], qu = pq[idx];
        float2 k01 = unpack_h2(ku.x), k23 = unpack_h2(ku.y);
        float2 v01 = unpack_h2(vu.x), v23 = unpack_h2(vu.y);
        float2 q01 = unpack_h2(qu.x), q23 = unpack_h2(qu.y);
        run.x += k01.x * v01.x; run.y += k01.y * v01.y;
        run.z += k23.x * v23.x; run.w += k23.y * v23.y;
        uint2 u;
        u.x = pack_h2(q01.x * run.x * SCALE, q01.y * run.y * SCALE);
        u.y = pack_h2(q23.x * run.z * SCALE, q23.y * run.w * SCALE);
        ctxh[idx] = u;
    }
}

// ---------------------------------------------------------------- launch
extern "C" void kernel_launch(void* const* d_in, const int* in_sizes, int n_in,
                              void* d_out, int out_size)
{
    const float* x  = (const float*)d_in[0];
    const float* Wq = (const float*)d_in[1];
    const float* bq = (const float*)d_in[2];
    const float* Wk = (const float*)d_in[3];
    const float* bk = (const float*)d_in[4];
    const float* Wv = (const float*)d_in[5];
    const float* bv = (const float*)d_in[6];
    const float* Wo = (const float*)d_in[7];
    const float* bo = (const float*)d_in[8];
    float* out = (float*)d_out;

    __half *xh, *wh, *ctxh, *phiq, *phik, *v;
    float *part;
    cudaGetSymbolAddress((void**)&xh,   g_xh);
    cudaGetSymbolAddress((void**)&wh,   g_wh);
    cudaGetSymbolAddress((void**)&ctxh, g_ctxh);
    cudaGetSymbolAddress((void**)&phiq, g_phiq);
    cudaGetSymbolAddress((void**)&phik, g_phik);
    cudaGetSymbolAddress((void**)&v,    g_v);
    cudaGetSymbolAddress((void**)&part, g_part);
    __half* whq = wh;
    __half* whk = wh + (size_t)Dm * Dm;
    __half* whv = wh + 2 * (size_t)Dm * Dm;
    __half* who = wh + 3 * (size_t)Dm * Dm;

    static bool attr_set = false;
    if (!attr_set) {
        cudaFuncSetAttribute(gemm_qkv, cudaFuncAttributeMaxDynamicSharedMemorySize, SMEM_TOTAL);
        cudaFuncSetAttribute(gemm_o,   cudaFuncAttributeMaxDynamicSharedMemorySize, SMEM_TOTAL);
        attr_set = true;
    }

    // one fused fp16 conversion pass for x + all four weights
    const int nTot = NX4 + 4 * NW4;
    to_half_all<<<(nTot + 255) / 256, 256>>>(
        (const float4*)x, (const float4*)Wq, (const float4*)Wk,
        (const float4*)Wv, (const float4*)Wo, (uint2*)xh, (uint2*)wh);

    dim3 qkvgrid(Dm / BN, Mtot / BM, 3);   // (8, 128, 3)
    gemm_qkv<<<qkvgrid, 256, SMEM_TOTAL>>>(xh, whq, bq, whk, bk, whv, bv,
                                           phiq, phik, v);

    dim3 pgrid(Dm / 4 / 256, NC, Bz);      // (2, 64, 4)
    chunk_partial<<<pgrid, 256>>>((const uint2*)phik, (const uint2*)v,
                                  (float4*)part);
    dim3 sgrid(Dm / 4 / 256, Bz);
    scan_partials<<<sgrid, 256>>>((float4*)part);
    apply_scan<<<pgrid, 256>>>((const uint2*)phiq, (const uint2*)phik,
                               (const uint2*)v, (const float4*)part,
                               (uint2*)ctxh);

    dim3 ogrid(Dm / BN, Mtot / BM);        // (8, 128)
    gemm_o<<<ogrid, 256, SMEM_TOTAL>>>(ctxh, who, bo, out);
}

// round 15
// speedup vs baseline: 1.0769x; 1.0484x over previous
#include <cuda_runtime.h>
#include <cuda_fp16.h>
#include <cstdint>
#include <math.h>

// ---------------------------------------------------------------- constants
constexpr int Bz   = 4;
constexpr int Lseq = 4096;
constexpr int Dm   = 2048;
constexpr int Mtot = Bz * Lseq;                 // 16384
constexpr float SCALE = 0.08838834764831845f;   // 128^-0.5

constexpr int NC = 64;                          // scan chunks
constexpr int CH = Lseq / NC;                   // 64

// GEMM tiling: CTA 128x256, 16 warps of 64x32, BK=64, 4-stage cp.async
constexpr int BM = 128, BN = 256, BK = 64;
constexpr int NTH = 512;
constexpr int STAGES = 4;
constexpr int KT = Dm / BK;                       // 32
constexpr int ROWB = 144;                         // 128B data + 16B pad
constexpr int A_TILE = BM * ROWB;                 // 18432 bytes
constexpr int B_TILE = BN * ROWB;                 // 36864 bytes
constexpr int STAGE_BYTES = A_TILE + B_TILE;      // 55296
constexpr int SMEM_TOTAL  = STAGES * STAGE_BYTES; // 221184

constexpr int NX4 = Mtot * Dm / 4;                // 8388608  (2^23)
constexpr int NW4 = Dm * Dm / 4;                  // 1048576  (2^20)

// ---------------------------------------------------------------- scratch
__device__ __half g_xh  [(size_t)Mtot * Dm];
__device__ __half g_wh  [4][(size_t)Dm * Dm];
__device__ __half g_phiq[(size_t)Mtot * Dm];
__device__ __half g_phik[(size_t)Mtot * Dm];
__device__ __half g_v   [(size_t)Mtot * Dm];
__device__ __half g_ctxh[(size_t)Mtot * Dm];
__device__ float  g_part[(size_t)Bz * NC * Dm];

// ---------------------------------------------------------------- helpers
__device__ __forceinline__ uint32_t smem_u32(const void* p) {
    uint32_t a;
    asm("{ .reg .u64 t; cvta.to.shared.u64 t, %1; cvt.u32.u64 %0, t; }"
        : "=r"(a) : "l"(p));
    return a;
}
__device__ __forceinline__ void cp16(uint32_t dst, const void* src) {
    asm volatile("cp.async.cg.shared.global [%0], [%1], 16;"
                 :: "r"(dst), "l"(src) : "memory");
}
__device__ __forceinline__ void mma_f16(float* d, const uint32_t* a,
                                        const uint32_t* b) {
    asm volatile(
        "mma.sync.aligned.m16n8k16.row.col.f32.f16.f16.f32 "
        "{%0,%1,%2,%3}, {%4,%5,%6,%7}, {%8,%9}, {%0,%1,%2,%3};"
        : "+f"(d[0]), "+f"(d[1]), "+f"(d[2]), "+f"(d[3])
        : "r"(a[0]), "r"(a[1]), "r"(a[2]), "r"(a[3]), "r"(b[0]), "r"(b[1]));
}
__device__ __forceinline__ void ldsm4(uint32_t* r, uint32_t addr) {
    asm volatile("ldmatrix.sync.aligned.m8n8.x4.shared.b16 {%0,%1,%2,%3}, [%4];"
                 : "=r"(r[0]), "=r"(r[1]), "=r"(r[2]), "=r"(r[3]) : "r"(addr));
}
__device__ __forceinline__ uint32_t pack_h2(float a, float b) {
    __half2 h = __floats2half2_rn(a, b);
    return *(const uint32_t*)&h;
}
__device__ __forceinline__ float2 unpack_h2(uint32_t u) {
    return __half22float2(*(const __half2*)&u);
}

// ------------------------------------------------------------------- GEMM
// C[M][N] = act(A[M][K] @ W[N][K]^T + bias[N]); fp16 in, fp32 accumulate.
// 512 threads = 16 warps (2m x 8n), warp tile 64x32 -> 4 warps/SMSP.
template<typename OutT>
__device__ __forceinline__ void gemm_body(
    const __half* __restrict__ A, const __half* __restrict__ W,
    const float* __restrict__ bias, OutT* __restrict__ C, int act)
{
    extern __shared__ float smem[];
    const uint32_t sb = smem_u32(smem);
    const int tid  = threadIdx.x;
    const int wid  = tid >> 5;
    const int lane = tid & 31;
    const int wm = wid & 1;             // 0..1 -> 64-row slab
    const int wn = wid >> 1;            // 0..7 -> 32-col slab
    const int gq = lane >> 2;
    const int gr = lane & 3;
    const int m0 = blockIdx.y * BM;
    const int n0 = blockIdx.x * BN;

    uint32_t offA[4], offB[2];
#pragma unroll
    for (int mt = 0; mt < 4; mt++) {
        int row = wm * 64 + mt * 16 + ((lane >> 3) & 1) * 8 + (lane & 7);
        offA[mt] = (uint32_t)(row * ROWB + ((lane >> 4) * 16));
    }
#pragma unroll
    for (int p = 0; p < 2; p++) {
        int row = wn * 32 + p * 16 + (lane >> 4) * 8 + (lane & 7);
        offB[p] = (uint32_t)(row * ROWB + (((lane >> 3) & 1) * 16));
    }

    float acc[4][4][4];
#pragma unroll
    for (int i = 0; i < 4; i++)
#pragma unroll
        for (int j = 0; j < 4; j++)
#pragma unroll
            for (int k = 0; k < 4; k++) acc[i][j][k] = 0.f;

    auto issue = [&](int kt) {
        const int s = kt & (STAGES - 1);
        const uint32_t dA = sb + s * STAGE_BYTES;
        const uint32_t dB = dA + A_TILE;
        const __half* Ag = A + (size_t)m0 * Dm + kt * BK;
        const __half* Wg = W + (size_t)n0 * Dm + kt * BK;
#pragma unroll
        for (int i = 0; i < 2; i++) {      // 128 rows x 8 chunks = 1024
            int ch = tid + NTH * i, row = ch >> 3, c4 = ch & 7;
            cp16(dA + row * ROWB + c4 * 16, Ag + (size_t)row * Dm + c4 * 8);
        }
#pragma unroll
        for (int i = 0; i < 4; i++) {      // 256 rows x 8 chunks = 2048
            int ch = tid + NTH * i, row = ch >> 3, c4 = ch & 7;
            cp16(dB + row * ROWB + c4 * 16, Wg + (size_t)row * Dm + c4 * 8);
        }
        asm volatile("cp.async.commit_group;" ::: "memory");
    };

    issue(0);
    issue(1);
    issue(2);

    for (int kt = 0; kt < KT; kt++) {
        const int s = kt & (STAGES - 1);
        asm volatile("cp.async.wait_group 2;" ::: "memory");
        __syncthreads();

        if (kt + 3 < KT) issue(kt + 3);
        else asm volatile("cp.async.commit_group;" ::: "memory");

        const uint32_t aBase = sb + s * STAGE_BYTES;
        const uint32_t bBase = aBase + A_TILE;

#pragma unroll
        for (int ks = 0; ks < 4; ks++) {
            const uint32_t kOfs = ks * 32;
            uint32_t af[4][4], bfr[8];
#pragma unroll
            for (int mt = 0; mt < 4; mt++)
                ldsm4(af[mt], aBase + offA[mt] + kOfs);
#pragma unroll
            for (int p = 0; p < 2; p++)
                ldsm4(&bfr[4 * p], bBase + offB[p] + kOfs);
#pragma unroll
            for (int mt = 0; mt < 4; mt++)
#pragma unroll
                for (int nt = 0; nt < 4; nt++)
                    mma_f16(acc[mt][nt], af[mt], &bfr[2 * nt]);
        }
    }

    // ----------------------------- epilogue --------------------------------
#pragma unroll
    for (int mt = 0; mt < 4; mt++) {
        const int r0 = m0 + wm * 64 + mt * 16 + gq;
#pragma unroll
        for (int nt = 0; nt < 4; nt++) {
            const int c0 = n0 + wn * 32 + nt * 8 + gr * 2;
            float b0 = bias[c0], b1 = bias[c0 + 1];
            float v0 = acc[mt][nt][0] + b0;
            float v1 = acc[mt][nt][1] + b1;
            float v2 = acc[mt][nt][2] + b0;
            float v3 = acc[mt][nt][3] + b1;
            if (act) {
                v0 = (v0 > 0.f) ? (v0 + 1.f) : expf(v0);
                v1 = (v1 > 0.f) ? (v1 + 1.f) : expf(v1);
                v2 = (v2 > 0.f) ? (v2 + 1.f) : expf(v2);
                v3 = (v3 > 0.f) ? (v3 + 1.f) : expf(v3);
            }
            if constexpr (sizeof(OutT) == 2) {
                *(uint32_t*)(C + (size_t)r0 * Dm + c0)       = pack_h2(v0, v1);
                *(uint32_t*)(C + (size_t)(r0 + 8) * Dm + c0) = pack_h2(v2, v3);
            } else {
                *(float2*)(C + (size_t)r0 * Dm + c0)       = make_float2(v0, v1);
                *(float2*)(C + (size_t)(r0 + 8) * Dm + c0) = make_float2(v2, v3);
            }
        }
    }
}

// fused QKV: blockIdx.z selects projection; outputs fp16
__global__ void __launch_bounds__(NTH, 1)
gemm_qkv(const __half* __restrict__ x,
         const __half* __restrict__ Wq, const float* __restrict__ bq,
         const __half* __restrict__ Wk, const float* __restrict__ bk,
         const __half* __restrict__ Wv, const float* __restrict__ bv,
         __half* __restrict__ phiq, __half* __restrict__ phik,
         __half* __restrict__ v)
{
    const int z = blockIdx.z;
    const __half* W   = (z == 0) ? Wq : (z == 1) ? Wk : Wv;
    const float* bias = (z == 0) ? bq : (z == 1) ? bk : bv;
    __half* C         = (z == 0) ? phiq : (z == 1) ? phik : v;
    gemm_body<__half>(x, W, bias, C, z < 2 ? 1 : 0);
}

__global__ void __launch_bounds__(NTH, 1)
gemm_o(const __half* __restrict__ A, const __half* __restrict__ W,
       const float* __restrict__ bias, float* __restrict__ C)
{
    gemm_body<float>(A, W, bias, C, 0);
}

// ------------------------------------------------------------ fused convert
__global__ void __launch_bounds__(256)
to_half_all(const float4* __restrict__ x,
            const float4* __restrict__ Wq, const float4* __restrict__ Wk,
            const float4* __restrict__ Wv, const float4* __restrict__ Wo,
            uint2* __restrict__ xh, uint2* __restrict__ wh)
{
    int i = blockIdx.x * 256 + threadIdx.x;
    const float4* src;
    uint2* dst;
    int j;
    if (i < NX4) {
        src = x; dst = xh; j = i;
    } else {
        int t = i - NX4;
        int r = t >> 20;           // NW4 = 2^20
        j = t & (NW4 - 1);
        src = (r == 0) ? Wq : (r == 1) ? Wk : (r == 2) ? Wv : Wo;
        dst = wh + (size_t)r * NW4;
    }
    float4 v = src[j];
    uint2 u;
    u.x = pack_h2(v.x, v.y);
    u.y = pack_h2(v.z, v.w);
    dst[j] = u;
}

// ---------------------------------------------------------------- scan stage
__global__ void chunk_partial(const uint2* __restrict__ pk,
                              const uint2* __restrict__ pv,
                              float4* __restrict__ part)
{
    constexpr int D4 = Dm / 4;
    const int d = blockIdx.x * 256 + threadIdx.x;
    const int c = blockIdx.y;
    const int b = blockIdx.z;
    size_t base = ((size_t)b * Lseq + (size_t)c * CH) * D4 + d;
    float4 s = make_float4(0.f, 0.f, 0.f, 0.f);
#pragma unroll 4
    for (int i = 0; i < CH; i++) {
        size_t idx = base + (size_t)i * D4;
        uint2 ku = pk[idx], vu = pv[idx];
        float2 k01 = unpack_h2(ku.x), k23 = unpack_h2(ku.y);
        float2 v01 = unpack_h2(vu.x), v23 = unpack_h2(vu.y);
        s.x += k01.x * v01.x; s.y += k01.y * v01.y;
        s.z += k23.x * v23.x; s.w += k23.y * v23.y;
    }
    part[((size_t)b * NC + c) * D4 + d] = s;
}

__global__ void scan_partials(float4* __restrict__ part)
{
    constexpr int D4 = Dm / 4;
    const int d = blockIdx.x * 256 + threadIdx.x;
    const int b = blockIdx.y;
    float4 run = make_float4(0.f, 0.f, 0.f, 0.f);
    for (int c = 0; c < NC; c++) {
        size_t idx = ((size_t)b * NC + c) * D4 + d;
        float4 t = part[idx];
        part[idx] = run;
        run.x += t.x; run.y += t.y; run.z += t.z; run.w += t.w;
    }
}

__global__ void apply_scan(const uint2* __restrict__ pq,
                           const uint2* __restrict__ pk,
                           const uint2* __restrict__ pv,
                           const float4* __restrict__ part,
                           uint2* __restrict__ ctxh)
{
    constexpr int D4 = Dm / 4;
    const int d = blockIdx.x * 256 + threadIdx.x;
    const int c = blockIdx.y;
    const int b = blockIdx.z;
    float4 run = part[((size_t)b * NC + c) * D4 + d];
    size_t base = ((size_t)b * Lseq + (size_t)c * CH) * D4 + d;
#pragma unroll 4
    for (int i = 0; i < CH; i++) {
        size_t idx = base + (size_t)i * D4;
        uint2 ku = pk[idx], vu = pv[idx], qu = pq[idx];
        float2 k01 = unpack_h2(ku.x), k23 = unpack_h2(ku.y);
        float2 v01 = unpack_h2(vu.x), v23 = unpack_h2(vu.y);
        float2 q01 = unpack_h2(qu.x), q23 = unpack_h2(qu.y);
        run.x += k01.x * v01.x; run.y += k01.y * v01.y;
        run.z += k23.x * v23.x; run.w += k23.y * v23.y;
        uint2 u;
        u.x = pack_h2(q01.x * run.x * SCALE, q01.y * run.y * SCALE);
        u.y = pack_h2(q23.x * run.z * SCALE, q23.y * run.w * SCALE);
        ctxh[idx] = u;
    }
}

// ---------------------------------------------------------------- launch
extern "C" void kernel_launch(void* const* d_in, const int* in_sizes, int n_in,
                              void* d_out, int out_size)
{
    const float* x  = (const float*)d_in[0];
    const float* Wq = (const float*)d_in[1];
    const float* bq = (const float*)d_in[2];
    const float* Wk = (const float*)d_in[3];
    const float* bk = (const float*)d_in[4];
    const float* Wv = (const float*)d_in[5];
    const float* bv = (const float*)d_in[6];
    const float* Wo = (const float*)d_in[7];
    const float* bo = (const float*)d_in[8];
    float* out = (float*)d_out;

    __half *xh, *wh, *ctxh, *phiq, *phik, *v;
    float *part;
    cudaGetSymbolAddress((void**)&xh,   g_xh);
    cudaGetSymbolAddress((void**)&wh,   g_wh);
    cudaGetSymbolAddress((void**)&ctxh, g_ctxh);
    cudaGetSymbolAddress((void**)&phiq, g_phiq);
    cudaGetSymbolAddress((void**)&phik, g_phik);
    cudaGetSymbolAddress((void**)&v,    g_v);
    cudaGetSymbolAddress((void**)&part, g_part);
    __half* whq = wh;
    __half* whk = wh + (size_t)Dm * Dm;
    __half* whv = wh + 2 * (size_t)Dm * Dm;
    __half* who = wh + 3 * (size_t)Dm * Dm;

    static bool attr_set = false;
    if (!attr_set) {
        cudaFuncSetAttribute(gemm_qkv, cudaFuncAttributeMaxDynamicSharedMemorySize, SMEM_TOTAL);
        cudaFuncSetAttribute(gemm_o,   cudaFuncAttributeMaxDynamicSharedMemorySize, SMEM_TOTAL);
        attr_set = true;
    }

    // one fused fp16 conversion pass for x + all four weights
    const int nTot = NX4 + 4 * NW4;
    to_half_all<<<(nTot + 255) / 256, 256>>>(
        (const float4*)x, (const float4*)Wq, (const float4*)Wk,
        (const float4*)Wv, (const float4*)Wo, (uint2*)xh, (uint2*)wh);

    dim3 qkvgrid(Dm / BN, Mtot / BM, 3);   // (8, 128, 3)
    gemm_qkv<<<qkvgrid, NTH, SMEM_TOTAL>>>(xh, whq, bq, whk, bk, whv, bv,
                                           phiq, phik, v);

    dim3 pgrid(Dm / 4 / 256, NC, Bz);      // (2, 64, 4)
    chunk_partial<<<pgrid, 256>>>((const uint2*)phik, (const uint2*)v,
                                  (float4*)part);
    dim3 sgrid(Dm / 4 / 256, Bz);
    scan_partials<<<sgrid, 256>>>((float4*)part);
    apply_scan<<<pgrid, 256>>>((const uint2*)phiq, (const uint2*)phik,
                               (const uint2*)v, (const float4*)part,
                               (uint2*)ctxh);

    dim3 ogrid(Dm / BN, Mtot / BM);        // (8, 128)
    gemm_o<<<ogrid, NTH, SMEM_TOTAL>>>(ctxh, who, bo, out);
}

// round 16
// speedup vs baseline: 1.1579x; 1.0752x over previous
#include <cuda_runtime.h>
#include <cuda_fp16.h>
#include <cstdint>
#include <math.h>

// ---------------------------------------------------------------- constants
constexpr int Bz   = 4;
constexpr int Lseq = 4096;
constexpr int Dm   = 2048;
constexpr int Mtot = Bz * Lseq;                 // 16384
constexpr float SCALE = 0.08838834764831845f;   // 128^-0.5

constexpr int NC = 64;                          // scan chunks
constexpr int CH = Lseq / NC;                   // 64

// GEMM tiling: CTA 128x128, 8 warps of 64x32, BK=64, 3-stage, 2 CTA/SM
constexpr int BM = 128, BN = 128, BK = 64;
constexpr int NTH = 256;
constexpr int STAGES = 3;
constexpr int KT = Dm / BK;                       // 32
constexpr int ROWB = 144;                         // 128B data + 16B pad
constexpr int A_TILE = BM * ROWB;                 // 18432 bytes
constexpr int B_TILE = BN * ROWB;                 // 18432 bytes
constexpr int STAGE_BYTES = A_TILE + B_TILE;      // 36864
constexpr int SMEM_TOTAL  = STAGES * STAGE_BYTES; // 110592

constexpr int NX4 = Mtot * Dm / 4;                // 8388608  (2^23)
constexpr int NW4 = Dm * Dm / 4;                  // 1048576  (2^20)

// ---------------------------------------------------------------- scratch
__device__ __half g_xh  [(size_t)Mtot * Dm];
__device__ __half g_wh  [4][(size_t)Dm * Dm];
__device__ __half g_phiq[(size_t)Mtot * Dm];
__device__ __half g_phik[(size_t)Mtot * Dm];
__device__ __half g_v   [(size_t)Mtot * Dm];
__device__ __half g_ctxh[(size_t)Mtot * Dm];
__device__ float  g_part[(size_t)Bz * NC * Dm];

// ---------------------------------------------------------------- helpers
__device__ __forceinline__ uint32_t smem_u32(const void* p) {
    uint32_t a;
    asm("{ .reg .u64 t; cvta.to.shared.u64 t, %1; cvt.u32.u64 %0, t; }"
        : "=r"(a) : "l"(p));
    return a;
}
__device__ __forceinline__ void cp16(uint32_t dst, const void* src) {
    asm volatile("cp.async.cg.shared.global [%0], [%1], 16;"
                 :: "r"(dst), "l"(src) : "memory");
}
__device__ __forceinline__ void mma_f16(float* d, const uint32_t* a,
                                        const uint32_t* b) {
    asm volatile(
        "mma.sync.aligned.m16n8k16.row.col.f32.f16.f16.f32 "
        "{%0,%1,%2,%3}, {%4,%5,%6,%7}, {%8,%9}, {%0,%1,%2,%3};"
        : "+f"(d[0]), "+f"(d[1]), "+f"(d[2]), "+f"(d[3])
        : "r"(a[0]), "r"(a[1]), "r"(a[2]), "r"(a[3]), "r"(b[0]), "r"(b[1]));
}
__device__ __forceinline__ void ldsm4(uint32_t* r, uint32_t addr) {
    asm volatile("ldmatrix.sync.aligned.m8n8.x4.shared.b16 {%0,%1,%2,%3}, [%4];"
                 : "=r"(r[0]), "=r"(r[1]), "=r"(r[2]), "=r"(r[3]) : "r"(addr));
}
__device__ __forceinline__ uint32_t pack_h2(float a, float b) {
    __half2 h = __floats2half2_rn(a, b);
    return *(const uint32_t*)&h;
}
__device__ __forceinline__ float2 unpack_h2(uint32_t u) {
    return __half22float2(*(const __half2*)&u);
}

// ------------------------------------------------------------------- GEMM
// C[M][N] = act(A[M][K] @ W[N][K]^T + bias[N]); fp16 in, fp32 accumulate.
// 256 threads = 8 warps (2m x 4n), warp tile 64x32; 2 CTAs/SM.
template<typename OutT>
__device__ __forceinline__ void gemm_body(
    const __half* __restrict__ A, const __half* __restrict__ W,
    const float* __restrict__ bias, OutT* __restrict__ C, int act)
{
    extern __shared__ float smem[];
    const uint32_t sb = smem_u32(smem);
    const int tid  = threadIdx.x;
    const int wid  = tid >> 5;
    const int lane = tid & 31;
    const int wm = wid & 1;             // 0..1 -> 64-row slab
    const int wn = wid >> 1;            // 0..3 -> 32-col slab
    const int gq = lane >> 2;
    const int gr = lane & 3;
    const int m0 = blockIdx.y * BM;
    const int n0 = blockIdx.x * BN;

    uint32_t offA[4], offB[2];
#pragma unroll
    for (int mt = 0; mt < 4; mt++) {
        int row = wm * 64 + mt * 16 + ((lane >> 3) & 1) * 8 + (lane & 7);
        offA[mt] = (uint32_t)(row * ROWB + ((lane >> 4) * 16));
    }
#pragma unroll
    for (int p = 0; p < 2; p++) {
        int row = wn * 32 + p * 16 + (lane >> 4) * 8 + (lane & 7);
        offB[p] = (uint32_t)(row * ROWB + (((lane >> 3) & 1) * 16));
    }

    float acc[4][4][4];
#pragma unroll
    for (int i = 0; i < 4; i++)
#pragma unroll
        for (int j = 0; j < 4; j++)
#pragma unroll
            for (int k = 0; k < 4; k++) acc[i][j][k] = 0.f;

    auto issue = [&](int kt) {
        const int s = kt % STAGES;
        const uint32_t dA = sb + s * STAGE_BYTES;
        const uint32_t dB = dA + A_TILE;
        const __half* Ag = A + (size_t)m0 * Dm + kt * BK;
        const __half* Wg = W + (size_t)n0 * Dm + kt * BK;
#pragma unroll
        for (int i = 0; i < 4; i++) {      // 128 rows x 8 chunks = 1024
            int ch = tid + NTH * i, row = ch >> 3, c4 = ch & 7;
            cp16(dA + row * ROWB + c4 * 16, Ag + (size_t)row * Dm + c4 * 8);
        }
#pragma unroll
        for (int i = 0; i < 4; i++) {
            int ch = tid + NTH * i, row = ch >> 3, c4 = ch & 7;
            cp16(dB + row * ROWB + c4 * 16, Wg + (size_t)row * Dm + c4 * 8);
        }
        asm volatile("cp.async.commit_group;" ::: "memory");
    };

    issue(0);
    issue(1);

    for (int kt = 0; kt < KT; kt++) {
        const int s = kt % STAGES;
        asm volatile("cp.async.wait_group 1;" ::: "memory");
        __syncthreads();

        if (kt + 2 < KT) issue(kt + 2);
        else asm volatile("cp.async.commit_group;" ::: "memory");

        const uint32_t aBase = sb + s * STAGE_BYTES;
        const uint32_t bBase = aBase + A_TILE;

#pragma unroll
        for (int ks = 0; ks < 4; ks++) {
            const uint32_t kOfs = ks * 32;
            uint32_t af[4][4], bfr[8];
#pragma unroll
            for (int mt = 0; mt < 4; mt++)
                ldsm4(af[mt], aBase + offA[mt] + kOfs);
#pragma unroll
            for (int p = 0; p < 2; p++)
                ldsm4(&bfr[4 * p], bBase + offB[p] + kOfs);
#pragma unroll
            for (int mt = 0; mt < 4; mt++)
#pragma unroll
                for (int nt = 0; nt < 4; nt++)
                    mma_f16(acc[mt][nt], af[mt], &bfr[2 * nt]);
        }
    }

    // ----------------------------- epilogue --------------------------------
#pragma unroll
    for (int mt = 0; mt < 4; mt++) {
        const int r0 = m0 + wm * 64 + mt * 16 + gq;
#pragma unroll
        for (int nt = 0; nt < 4; nt++) {
            const int c0 = n0 + wn * 32 + nt * 8 + gr * 2;
            float b0 = bias[c0], b1 = bias[c0 + 1];
            float v0 = acc[mt][nt][0] + b0;
            float v1 = acc[mt][nt][1] + b1;
            float v2 = acc[mt][nt][2] + b0;
            float v3 = acc[mt][nt][3] + b1;
            if (act) {
                v0 = (v0 > 0.f) ? (v0 + 1.f) : expf(v0);
                v1 = (v1 > 0.f) ? (v1 + 1.f) : expf(v1);
                v2 = (v2 > 0.f) ? (v2 + 1.f) : expf(v2);
                v3 = (v3 > 0.f) ? (v3 + 1.f) : expf(v3);
            }
            if constexpr (sizeof(OutT) == 2) {
                *(uint32_t*)(C + (size_t)r0 * Dm + c0)       = pack_h2(v0, v1);
                *(uint32_t*)(C + (size_t)(r0 + 8) * Dm + c0) = pack_h2(v2, v3);
            } else {
                *(float2*)(C + (size_t)r0 * Dm + c0)       = make_float2(v0, v1);
                *(float2*)(C + (size_t)(r0 + 8) * Dm + c0) = make_float2(v2, v3);
            }
        }
    }
}

// fused QKV: blockIdx.z selects projection; outputs fp16
__global__ void __launch_bounds__(NTH, 2)
gemm_qkv(const __half* __restrict__ x,
         const __half* __restrict__ Wq, const float* __restrict__ bq,
         const __half* __restrict__ Wk, const float* __restrict__ bk,
         const __half* __restrict__ Wv, const float* __restrict__ bv,
         __half* __restrict__ phiq, __half* __restrict__ phik,
         __half* __restrict__ v)
{
    const int z = blockIdx.z;
    const __half* W   = (z == 0) ? Wq : (z == 1) ? Wk : Wv;
    const float* bias = (z == 0) ? bq : (z == 1) ? bk : bv;
    __half* C         = (z == 0) ? phiq : (z == 1) ? phik : v;
    gemm_body<__half>(x, W, bias, C, z < 2 ? 1 : 0);
}

__global__ void __launch_bounds__(NTH, 2)
gemm_o(const __half* __restrict__ A, const __half* __restrict__ W,
       const float* __restrict__ bias, float* __restrict__ C)
{
    gemm_body<float>(A, W, bias, C, 0);
}

// ------------------------------------------------------------ fused convert
__global__ void __launch_bounds__(256)
to_half_all(const float4* __restrict__ x,
            const float4* __restrict__ Wq, const float4* __restrict__ Wk,
            const float4* __restrict__ Wv, const float4* __restrict__ Wo,
            uint2* __restrict__ xh, uint2* __restrict__ wh)
{
    int i = blockIdx.x * 256 + threadIdx.x;
    const float4* src;
    uint2* dst;
    int j;
    if (i < NX4) {
        src = x; dst = xh; j = i;
    } else {
        int t = i - NX4;
        int r = t >> 20;           // NW4 = 2^20
        j = t & (NW4 - 1);
        src = (r == 0) ? Wq : (r == 1) ? Wk : (r == 2) ? Wv : Wo;
        dst = wh + (size_t)r * NW4;
    }
    float4 v = src[j];
    uint2 u;
    u.x = pack_h2(v.x, v.y);
    u.y = pack_h2(v.z, v.w);
    dst[j] = u;
}

// ---------------------------------------------------------------- scan stage
__global__ void chunk_partial(const uint2* __restrict__ pk,
                              const uint2* __restrict__ pv,
                              float4* __restrict__ part)
{
    constexpr int D4 = Dm / 4;
    const int d = blockIdx.x * 256 + threadIdx.x;
    const int c = blockIdx.y;
    const int b = blockIdx.z;
    size_t base = ((size_t)b * Lseq + (size_t)c * CH) * D4 + d;
    float4 s = make_float4(0.f, 0.f, 0.f, 0.f);
#pragma unroll 4
    for (int i = 0; i < CH; i++) {
        size_t idx = base + (size_t)i * D4;
        uint2 ku = pk[idx], vu = pv[idx];
        float2 k01 = unpack_h2(ku.x), k23 = unpack_h2(ku.y);
        float2 v01 = unpack_h2(vu.x), v23 = unpack_h2(vu.y);
        s.x += k01.x * v01.x; s.y += k01.y * v01.y;
        s.z += k23.x * v23.x; s.w += k23.y * v23.y;
    }
    part[((size_t)b * NC + c) * D4 + d] = s;
}

__global__ void scan_partials(float4* __restrict__ part)
{
    constexpr int D4 = Dm / 4;
    const int d = blockIdx.x * 256 + threadIdx.x;
    const int b = blockIdx.y;
    float4 run = make_float4(0.f, 0.f, 0.f, 0.f);
    for (int c = 0; c < NC; c++) {
        size_t idx = ((size_t)b * NC + c) * D4 + d;
        float4 t = part[idx];
        part[idx] = run;
        run.x += t.x; run.y += t.y; run.z += t.z; run.w += t.w;
    }
}

__global__ void apply_scan(const uint2* __restrict__ pq,
                           const uint2* __restrict__ pk,
                           const uint2* __restrict__ pv,
                           const float4* __restrict__ part,
                           uint2* __restrict__ ctxh)
{
    constexpr int D4 = Dm / 4;
    const int d = blockIdx.x * 256 + threadIdx.x;
    const int c = blockIdx.y;
    const int b = blockIdx.z;
    float4 run = part[((size_t)b * NC + c) * D4 + d];
    size_t base = ((size_t)b * Lseq + (size_t)c * CH) * D4 + d;
#pragma unroll 4
    for (int i = 0; i < CH; i++) {
        size_t idx = base + (size_t)i * D4;
        uint2 ku = pk[idx], vu = pv[idx], qu = pq[idx];
        float2 k01 = unpack_h2(ku.x), k23 = unpack_h2(ku.y);
        float2 v01 = unpack_h2(vu.x), v23 = unpack_h2(vu.y);
        float2 q01 = unpack_h2(qu.x), q23 = unpack_h2(qu.y);
        run.x += k01.x * v01.x; run.y += k01.y * v01.y;
        run.z += k23.x * v23.x; run.w += k23.y * v23.y;
        uint2 u;
        u.x = pack_h2(q01.x * run.x * SCALE, q01.y * run.y * SCALE);
        u.y = pack_h2(q23.x * run.z * SCALE, q23.y * run.w * SCALE);
        ctxh[idx] = u;
    }
}

// ---------------------------------------------------------------- launch
extern "C" void kernel_launch(void* const* d_in, const int* in_sizes, int n_in,
                              void* d_out, int out_size)
{
    const float* x  = (const float*)d_in[0];
    const float* Wq = (const float*)d_in[1];
    const float* bq = (const float*)d_in[2];
    const float* Wk = (const float*)d_in[3];
    const float* bk = (const float*)d_in[4];
    const float* Wv = (const float*)d_in[5];
    const float* bv = (const float*)d_in[6];
    const float* Wo = (const float*)d_in[7];
    const float* bo = (const float*)d_in[8];
    float* out = (float*)d_out;

    __half *xh, *wh, *ctxh, *phiq, *phik, *v;
    float *part;
    cudaGetSymbolAddress((void**)&xh,   g_xh);
    cudaGetSymbolAddress((void**)&wh,   g_wh);
    cudaGetSymbolAddress((void**)&ctxh, g_ctxh);
    cudaGetSymbolAddress((void**)&phiq, g_phiq);
    cudaGetSymbolAddress((void**)&phik, g_phik);
    cudaGetSymbolAddress((void**)&v,    g_v);
    cudaGetSymbolAddress((void**)&part, g_part);
    __half* whq = wh;
    __half* whk = wh + (size_t)Dm * Dm;
    __half* whv = wh + 2 * (size_t)Dm * Dm;
    __half* who = wh + 3 * (size_t)Dm * Dm;

    static bool attr_set = false;
    if (!attr_set) {
        cudaFuncSetAttribute(gemm_qkv, cudaFuncAttributeMaxDynamicSharedMemorySize, SMEM_TOTAL);
        cudaFuncSetAttribute(gemm_o,   cudaFuncAttributeMaxDynamicSharedMemorySize, SMEM_TOTAL);
        attr_set = true;
    }

    // one fused fp16 conversion pass for x + all four weights
    const int nTot = NX4 + 4 * NW4;
    to_half_all<<<(nTot + 255) / 256, 256>>>(
        (const float4*)x, (const float4*)Wq, (const float4*)Wk,
        (const float4*)Wv, (const float4*)Wo, (uint2*)xh, (uint2*)wh);

    dim3 qkvgrid(Dm / BN, Mtot / BM, 3);   // (16, 128, 3)
    gemm_qkv<<<qkvgrid, NTH, SMEM_TOTAL>>>(xh, whq, bq, whk, bk, whv, bv,
                                           phiq, phik, v);

    dim3 pgrid(Dm / 4 / 256, NC, Bz);      // (2, 64, 4)
    chunk_partial<<<pgrid, 256>>>((const uint2*)phik, (const uint2*)v,
                                  (float4*)part);
    dim3 sgrid(Dm / 4 / 256, Bz);
    scan_partials<<<sgrid, 256>>>((float4*)part);
    apply_scan<<<pgrid, 256>>>((const uint2*)phiq, (const uint2*)phik,
                               (const uint2*)v, (const float4*)part,
                               (uint2*)ctxh);

    dim3 ogrid(Dm / BN, Mtot / BM);        // (16, 128)
    gemm_o<<<ogrid, NTH, SMEM_TOTAL>>>(ctxh, who, bo, out);
}